// round 1
// baseline (speedup 1.0000x reference)
#include <cuda_runtime.h>

// Shapes (fixed by the problem)
#define B_   64
#define C_   256
#define N_   307
#define T_   12
#define NT   3684          // N_*T_

// Scratch (allocation-free rule: __device__ globals)
__device__ float g_k  [B_ * C_ * T_];        // pooled keys   [B,C,T]
__device__ float g_kW [B_ * C_ * T_];        // k @ W         [B,C,T]
__device__ float g_att[(size_t)B_ * C_ * C_]; // softmax attn [B,C,C]  (16.8 MB)

// ---------------------------------------------------------------------------
// Kernel 1: k[b,c,t] = sum_i x[b,c,i,t] * alpha[i];  kW[b,c,s] = sum_t k*W[t,s]
// 384 threads: 384 % 12 == 0 -> each thread owns ONE fixed t (no spilled acc[]).
// ---------------------------------------------------------------------------
__global__ __launch_bounds__(384) void k1_pool(const float* __restrict__ x,
                                               const float* __restrict__ W,
                                               const float* __restrict__ alpha) {
    __shared__ float sal[N_];
    __shared__ float sred[384];
    __shared__ float kk[T_];

    const int tid = threadIdx.x;
    const int c = blockIdx.x, b = blockIdx.y;

    for (int i = tid; i < N_; i += 384) sal[i] = alpha[i];
    __syncthreads();

    const float* xp = x + (size_t)(b * C_ + c) * NT;
    float acc = 0.f;
    for (int j = tid; j < NT; j += 384)   // t = j % 12 is invariant = tid % 12
        acc += xp[j] * sal[j / T_];
    sred[tid] = acc;
    __syncthreads();

    if (tid < T_) {
        float s = 0.f;
        #pragma unroll
        for (int g = 0; g < 32; g++) s += sred[tid + T_ * g];  // all share t == tid
        kk[tid] = s;
        g_k[(b * C_ + c) * T_ + tid] = s;
    }
    __syncthreads();
    if (tid < T_) {
        float s = 0.f;
        #pragma unroll
        for (int t = 0; t < T_; t++) s += kk[t] * W[t * T_ + tid];
        g_kW[(b * C_ + c) * T_ + tid] = s;
    }
}

// ---------------------------------------------------------------------------
// Kernel 2: scores[b,c,d] = sum_t kW[b,c,t]*k[b,d,t]; softmax over d -> att.
// One block per (b,c), 256 threads (thread == d). k[b] staged in shared with
// stride-13 padding (gcd(13,32)=1 => conflict-free strided reads).
// ---------------------------------------------------------------------------
__global__ __launch_bounds__(256) void k2_att() {
    __shared__ float kb[C_ * 13];
    __shared__ float kw[T_];
    __shared__ float red[8];

    const int tid = threadIdx.x;
    const int c = blockIdx.x, b = blockIdx.y;

    for (int idx = tid; idx < C_ * T_; idx += 256)
        kb[(idx / T_) * 13 + (idx % T_)] = g_k[b * C_ * T_ + idx];
    if (tid < T_) kw[tid] = g_kW[(b * C_ + c) * T_ + tid];
    __syncthreads();

    float s = 0.f;
    #pragma unroll
    for (int t = 0; t < T_; t++) s += kw[t] * kb[tid * 13 + t];

    // block max
    float m = s;
    #pragma unroll
    for (int o = 16; o; o >>= 1) m = fmaxf(m, __shfl_xor_sync(0xffffffffu, m, o));
    if ((tid & 31) == 0) red[tid >> 5] = m;
    __syncthreads();
    float bm = red[0];
    #pragma unroll
    for (int w = 1; w < 8; w++) bm = fmaxf(bm, red[w]);

    float p = __expf(s - bm);

    // block sum
    float ps = p;
    #pragma unroll
    for (int o = 16; o; o >>= 1) ps += __shfl_xor_sync(0xffffffffu, ps, o);
    __syncthreads();                       // red reuse
    if ((tid & 31) == 0) red[tid >> 5] = ps;
    __syncthreads();
    float tot = 0.f;
    #pragma unroll
    for (int w = 0; w < 8; w++) tot += red[w];

    g_att[((size_t)(b * C_ + c)) * C_ + tid] = p / tot;
}

// ---------------------------------------------------------------------------
// Kernel 3: out[b] = att[b] (256x256) @ x[b] (256x3684), batched, fp32.
// Tiles: BM=128, BN=64, BK=16; 256 threads; 8x4 micro-tile per thread.
// As stored transposed [BK][BM] so a-frags are float4 LDS.
// ---------------------------------------------------------------------------
#define BM 128
#define BN 64
#define BK 16

__global__ __launch_bounds__(256) void k3_mix(const float* __restrict__ x,
                                              float* __restrict__ out) {
    __shared__ float As[BK][BM];   // 8 KB
    __shared__ float Bs[BK][BN];   // 4 KB

    const int tid = threadIdx.x;
    const int b  = blockIdx.z;
    const int m0 = blockIdx.y * BM;
    const int n0 = blockIdx.x * BN;

    const float* A  = g_att + (size_t)b * C_ * C_;
    const float* Bm = x     + (size_t)b * C_ * NT;
    float*       Cm = out   + (size_t)b * C_ * NT;

    const int aRow = tid >> 2;          // 0..63
    const int aCol = (tid & 3) << 2;    // 0,4,8,12
    const int bRow = tid >> 4;          // 0..15
    const int bCol = (tid & 15) << 2;   // 0..60

    const int tx = tid & 15;            // 16 cols of 4
    const int ty = tid >> 4;            // 16 rows of 8

    float acc[8][4];
    #pragma unroll
    for (int i = 0; i < 8; i++)
        #pragma unroll
        for (int j = 0; j < 4; j++) acc[i][j] = 0.f;

    for (int k0 = 0; k0 < C_; k0 += BK) {
        // --- load att tile (128x16), transpose into As[BK][BM] ---
        #pragma unroll
        for (int r = 0; r < 2; r++) {
            const float4 v = *reinterpret_cast<const float4*>(
                &A[(size_t)(m0 + aRow + 64 * r) * C_ + k0 + aCol]);
            As[aCol + 0][aRow + 64 * r] = v.x;
            As[aCol + 1][aRow + 64 * r] = v.y;
            As[aCol + 2][aRow + 64 * r] = v.z;
            As[aCol + 3][aRow + 64 * r] = v.w;
        }
        // --- load x tile (16x64) ---
        {
            const int col = n0 + bCol;
            float4 v = make_float4(0.f, 0.f, 0.f, 0.f);
            if (col < NT)   // NT%4==0 -> float4 at col<NT is fully in-bounds
                v = *reinterpret_cast<const float4*>(&Bm[(size_t)(k0 + bRow) * NT + col]);
            *reinterpret_cast<float4*>(&Bs[bRow][bCol]) = v;
        }
        __syncthreads();

        #pragma unroll
        for (int k = 0; k < BK; k++) {
            const float4 a0 = *reinterpret_cast<const float4*>(&As[k][ty * 8]);
            const float4 a1 = *reinterpret_cast<const float4*>(&As[k][ty * 8 + 4]);
            const float4 b0 = *reinterpret_cast<const float4*>(&Bs[k][tx * 4]);
            const float a[8] = {a0.x, a0.y, a0.z, a0.w, a1.x, a1.y, a1.z, a1.w};
            const float bb[4] = {b0.x, b0.y, b0.z, b0.w};
            #pragma unroll
            for (int i = 0; i < 8; i++)
                #pragma unroll
                for (int j = 0; j < 4; j++)
                    acc[i][j] += a[i] * bb[j];
        }
        __syncthreads();
    }

    const int col = n0 + tx * 4;
    if (col < NT) {
        #pragma unroll
        for (int i = 0; i < 8; i++) {
            const int row = m0 + ty * 8 + i;
            const float4 v = make_float4(acc[i][0], acc[i][1], acc[i][2], acc[i][3]);
            *reinterpret_cast<float4*>(&Cm[(size_t)row * NT + col]) = v;
        }
    }
}

// ---------------------------------------------------------------------------
extern "C" void kernel_launch(void* const* d_in, const int* in_sizes, int n_in,
                              void* d_out, int out_size) {
    const float* x     = (const float*)d_in[0];
    const float* W     = (const float*)d_in[1];
    const float* alpha = (const float*)d_in[2];
    float* out = (float*)d_out;

    k1_pool<<<dim3(C_, B_), 384>>>(x, W, alpha);
    k2_att <<<dim3(C_, B_), 256>>>();
    k3_mix <<<dim3((NT + BN - 1) / BN, C_ / BM, B_), 256>>>(x, out);
}

// round 6
// speedup vs baseline: 1.8764x; 1.8764x over previous
#include <cuda_runtime.h>
#include <cuda_bf16.h>
#include <cstdint>

// Shapes (fixed)
#define B_   64
#define C_   256
#define N_   307
#define T_   12
#define NT   3684          // N_*T_
#define NT4  921           // NT/4

// ------------------------- scratch (__device__ globals) ---------------------
__device__ float g_k [B_ * C_ * T_];
__device__ float g_kW[B_ * C_ * T_];
__device__ __nv_bfloat16 g_xhi[(size_t)B_ * C_ * NT];
__device__ __nv_bfloat16 g_xlo[(size_t)B_ * C_ * NT];
__device__ __nv_bfloat16 g_ahi[(size_t)B_ * C_ * C_];
__device__ __nv_bfloat16 g_alo[(size_t)B_ * C_ * C_];

// ------------------------- PTX helpers (portable, sm_80+) -------------------
__device__ __forceinline__ uint32_t smem_u32(const void* p) {
    uint32_t a;
    asm("{ .reg .u64 t; cvta.to.shared.u64 t, %1; cvt.u32.u64 %0, t; }" : "=r"(a) : "l"(p));
    return a;
}
#define CP_ASYNC16(s, g) \
    asm volatile("cp.async.cg.shared.global [%0], [%1], 16;" :: "r"(s), "l"(g))
#define CP_ASYNC8Z(s, g, sz) \
    asm volatile("cp.async.ca.shared.global [%0], [%1], 8, %2;" :: "r"(s), "l"(g), "r"(sz))
#define CP_COMMIT() asm volatile("cp.async.commit_group;" ::: "memory")
#define CP_WAIT(n)  asm volatile("cp.async.wait_group %0;" :: "n"(n) : "memory")

#define LDSM_X4(r0, r1, r2, r3, a) \
    asm volatile("ldmatrix.sync.aligned.m8n8.x4.shared.b16 {%0,%1,%2,%3}, [%4];" \
        : "=r"(r0), "=r"(r1), "=r"(r2), "=r"(r3) : "r"(a))
#define LDSM_X4T(r0, r1, r2, r3, a) \
    asm volatile("ldmatrix.sync.aligned.m8n8.x4.trans.shared.b16 {%0,%1,%2,%3}, [%4];" \
        : "=r"(r0), "=r"(r1), "=r"(r2), "=r"(r3) : "r"(a))

#define MMA16816(d, a0, a1, a2, a3, b0, b1) \
    asm volatile("mma.sync.aligned.m16n8k16.row.col.f32.bf16.bf16.f32 " \
        "{%0,%1,%2,%3}, {%4,%5,%6,%7}, {%8,%9}, {%0,%1,%2,%3};" \
        : "+f"((d)[0]), "+f"((d)[1]), "+f"((d)[2]), "+f"((d)[3]) \
        : "r"(a0), "r"(a1), "r"(a2), "r"(a3), "r"(b0), "r"(b1))

// ---------------------------------------------------------------------------
// k1: pooled keys + kW, fused with bf16 hi/lo split-write of x.
// 384 threads; float4 per thread; a float4 never straddles a t=12 boundary
// (4*j4 mod 12 in {0,4,8}), so node index i = j4/3 is constant per float4.
// ---------------------------------------------------------------------------
__global__ __launch_bounds__(384) void k1_pool(const float* __restrict__ x,
                                               const float* __restrict__ W,
                                               const float* __restrict__ alpha) {
    __shared__ float sal[N_];
    __shared__ float sredf[384 * 4];
    __shared__ float kk[T_];

    const int tid = threadIdx.x;
    const int c = blockIdx.x, b = blockIdx.y;

    for (int i = tid; i < N_; i += 384) sal[i] = alpha[i];
    __syncthreads();

    const size_t rowoff = (size_t)(b * C_ + c) * NT;
    const float4* xp4 = reinterpret_cast<const float4*>(x + rowoff);
    __nv_bfloat16* xh = g_xhi + rowoff;
    __nv_bfloat16* xl = g_xlo + rowoff;

    float4 acc = make_float4(0.f, 0.f, 0.f, 0.f);
    #pragma unroll
    for (int u = 0; u < 3; u++) {
        const int j4 = tid + u * 384;
        if (j4 < NT4) {
            const float4 v = xp4[j4];
            const float a = sal[j4 / 3];
            acc.x += v.x * a; acc.y += v.y * a; acc.z += v.z * a; acc.w += v.w * a;

            union { __nv_bfloat16 h[4]; uint2 u2; } H, L;
            H.h[0] = __float2bfloat16(v.x); L.h[0] = __float2bfloat16(v.x - __bfloat162float(H.h[0]));
            H.h[1] = __float2bfloat16(v.y); L.h[1] = __float2bfloat16(v.y - __bfloat162float(H.h[1]));
            H.h[2] = __float2bfloat16(v.z); L.h[2] = __float2bfloat16(v.z - __bfloat162float(H.h[2]));
            H.h[3] = __float2bfloat16(v.w); L.h[3] = __float2bfloat16(v.w - __bfloat162float(H.h[3]));
            reinterpret_cast<uint2*>(xh)[j4] = H.u2;
            reinterpret_cast<uint2*>(xl)[j4] = L.u2;
        }
    }
    sredf[tid * 4 + 0] = acc.x;
    sredf[tid * 4 + 1] = acc.y;
    sredf[tid * 4 + 2] = acc.z;
    sredf[tid * 4 + 3] = acc.w;
    __syncthreads();

    if (tid < T_) {
        const int g = tid >> 2, e = tid & 3;   // t = 4*g + e; contributors have tid%3==g
        float s = 0.f;
        for (int q = 0; q < 128; q++) s += sredf[(3 * q + g) * 4 + e];
        kk[tid] = s;
        g_k[(b * C_ + c) * T_ + tid] = s;
    }
    __syncthreads();
    if (tid < T_) {
        float s = 0.f;
        #pragma unroll
        for (int t = 0; t < T_; t++) s += kk[t] * W[t * T_ + tid];
        g_kW[(b * C_ + c) * T_ + tid] = s;
    }
}

// ---------------------------------------------------------------------------
// k2: scores + softmax -> att, written as bf16 hi/lo split.
// ---------------------------------------------------------------------------
__global__ __launch_bounds__(256) void k2_att() {
    __shared__ float kb[C_ * 13];
    __shared__ float kw[T_];
    __shared__ float red[8];

    const int tid = threadIdx.x;
    const int c = blockIdx.x, b = blockIdx.y;

    for (int idx = tid; idx < C_ * T_; idx += 256)
        kb[(idx / T_) * 13 + (idx % T_)] = g_k[b * C_ * T_ + idx];
    if (tid < T_) kw[tid] = g_kW[(b * C_ + c) * T_ + tid];
    __syncthreads();

    float s = 0.f;
    #pragma unroll
    for (int t = 0; t < T_; t++) s += kw[t] * kb[tid * 13 + t];

    float m = s;
    #pragma unroll
    for (int o = 16; o; o >>= 1) m = fmaxf(m, __shfl_xor_sync(0xffffffffu, m, o));
    if ((tid & 31) == 0) red[tid >> 5] = m;
    __syncthreads();
    float bm = red[0];
    #pragma unroll
    for (int w = 1; w < 8; w++) bm = fmaxf(bm, red[w]);

    const float p = __expf(s - bm);

    float ps = p;
    #pragma unroll
    for (int o = 16; o; o >>= 1) ps += __shfl_xor_sync(0xffffffffu, ps, o);
    __syncthreads();
    if ((tid & 31) == 0) red[tid >> 5] = ps;
    __syncthreads();
    float tot = 0.f;
    #pragma unroll
    for (int w = 0; w < 8; w++) tot += red[w];

    const float v = p / tot;
    const __nv_bfloat16 hi = __float2bfloat16(v);
    const __nv_bfloat16 lo = __float2bfloat16(v - __bfloat162float(hi));
    const size_t idx = ((size_t)(b * C_ + c)) * C_ + tid;
    g_ahi[idx] = hi;
    g_alo[idx] = lo;
}

// ---------------------------------------------------------------------------
// k3: out[b] = att[b] @ x[b] via mma.sync bf16 (3-term split precision:
// hi*hi + hi*lo + lo*hi; lo*lo term ~2^-16 of hi*hi, dropped).
// Block: 128x128, K-chunk 32, 8 warps (2m x 4n), 64x32 per warp.
// A tiles [m][k] (pad 40), B tiles [k][n] gmem-layout (pad 136) + ldmatrix.trans.
// cp.async double-buffered.
// ---------------------------------------------------------------------------
#define BK 32
#define AS_STRIDE 40                       // elems; 80 B rows (conflict-free ldsm)
#define BS_STRIDE 136                      // elems; 272 B rows (conflict-free ldsm)
#define AS_BYTES (128 * AS_STRIDE * 2)     // 10240
#define BS_BYTES (BK * BS_STRIDE * 2)      // 8704
#define ST_AH 0
#define ST_AL AS_BYTES
#define ST_BH (2 * AS_BYTES)
#define ST_BL (2 * AS_BYTES + BS_BYTES)
#define STAGE_BYTES (2 * AS_BYTES + 2 * BS_BYTES)   // 37888
#define K3_SMEM (2 * STAGE_BYTES)                   // 75776

__global__ __launch_bounds__(256, 1) void k3_mma(float* __restrict__ out) {
    extern __shared__ char smem[];
    const uint32_t sbase = smem_u32(smem);
    const int tid = threadIdx.x, wid = tid >> 5, lane = tid & 31;
    const int b = blockIdx.z;
    const int m0 = blockIdx.y * 128;
    const int n0 = blockIdx.x * 128;
    const int wm = wid >> 2;               // 0..1 -> m half (64 rows)
    const int wn = wid & 3;                // 0..3 -> n quarter (32 cols)

    const __nv_bfloat16* Ah = g_ahi + ((size_t)(b * C_ + m0)) * C_;
    const __nv_bfloat16* Al = g_alo + ((size_t)(b * C_ + m0)) * C_;
    const __nv_bfloat16* Xh = g_xhi + (size_t)b * C_ * NT;
    const __nv_bfloat16* Xl = g_xlo + (size_t)b * C_ * NT;

    // ---- async stage loader ----
    auto load_stage = [&](int kc) {
        const int k0 = kc * BK;
        const uint32_t st = sbase + (kc & 1) * STAGE_BYTES;
        // A: 128 rows x 32 k, 16B chunks (512 per matrix), 2 per thread
        #pragma unroll
        for (int it = 0; it < 2; it++) {
            const int q = tid + it * 256;
            const int r = q >> 2, cc = q & 3;
            const uint32_t so = (uint32_t)(r * (AS_STRIDE * 2) + cc * 16);
            CP_ASYNC16(st + ST_AH + so, (const char*)(Ah + (size_t)r * C_ + k0 + cc * 8));
            CP_ASYNC16(st + ST_AL + so, (const char*)(Al + (size_t)r * C_ + k0 + cc * 8));
        }
        // B: 32 k-rows x 128 n, 8B chunks (1024 per matrix), 4 per thread
        #pragma unroll
        for (int it = 0; it < 4; it++) {
            const int q = tid + it * 256;
            const int kr = q >> 5, nc = q & 31;
            const int col = n0 + nc * 4;
            const uint32_t sz = (col < NT) ? 8u : 0u;
            const size_t go = (size_t)(k0 + kr) * NT + (col < NT ? col : 0);
            const uint32_t so = (uint32_t)(kr * (BS_STRIDE * 2) + nc * 8);
            CP_ASYNC8Z(st + ST_BH + so, (const char*)(Xh + go), sz);
            CP_ASYNC8Z(st + ST_BL + so, (const char*)(Xl + go), sz);
        }
        CP_COMMIT();
    };

    float acc[4][4][4];
    #pragma unroll
    for (int i = 0; i < 4; i++)
        #pragma unroll
        for (int j = 0; j < 4; j++)
            #pragma unroll
            for (int e = 0; e < 4; e++) acc[i][j][e] = 0.f;

    load_stage(0);

    for (int kc = 0; kc < 8; kc++) {
        if (kc < 7) load_stage(kc + 1);
        if (kc < 7) { CP_WAIT(1); } else { CP_WAIT(0); }
        __syncthreads();

        const uint32_t st = sbase + (kc & 1) * STAGE_BYTES;

        #pragma unroll
        for (int ks = 0; ks < 2; ks++) {
            const int kk0 = ks * 16;
            // A fragments: 4 m-tiles x (hi, lo)
            uint32_t ah[4][4], al[4][4];
            {
                const int arow = wm * 64 + (lane & 15);
                const int akc = kk0 + (lane >> 4) * 8;
                #pragma unroll
                for (int mi = 0; mi < 4; mi++) {
                    const uint32_t ao = (uint32_t)((arow + mi * 16) * (AS_STRIDE * 2) + akc * 2);
                    LDSM_X4(ah[mi][0], ah[mi][1], ah[mi][2], ah[mi][3], st + ST_AH + ao);
                    LDSM_X4(al[mi][0], al[mi][1], al[mi][2], al[mi][3], st + ST_AL + ao);
                }
            }
            // B fragments: 4 n8-tiles x (hi, lo) via 2 x4.trans per matrix
            uint32_t bh[8], bl[8];
            {
                const int brow = kk0 + (lane & 15);
                const int bnc = wn * 32 + (lane >> 4) * 8;
                #pragma unroll
                for (int g = 0; g < 2; g++) {
                    const uint32_t bo = (uint32_t)(brow * (BS_STRIDE * 2) + (bnc + g * 16) * 2);
                    LDSM_X4T(bh[4 * g + 0], bh[4 * g + 1], bh[4 * g + 2], bh[4 * g + 3],
                             st + ST_BH + bo);
                    LDSM_X4T(bl[4 * g + 0], bl[4 * g + 1], bl[4 * g + 2], bl[4 * g + 3],
                             st + ST_BL + bo);
                }
            }
            #pragma unroll
            for (int mi = 0; mi < 4; mi++)
                #pragma unroll
                for (int ni = 0; ni < 4; ni++) {
                    MMA16816(acc[mi][ni], ah[mi][0], ah[mi][1], ah[mi][2], ah[mi][3],
                             bh[2 * ni], bh[2 * ni + 1]);
                    MMA16816(acc[mi][ni], ah[mi][0], ah[mi][1], ah[mi][2], ah[mi][3],
                             bl[2 * ni], bl[2 * ni + 1]);
                    MMA16816(acc[mi][ni], al[mi][0], al[mi][1], al[mi][2], al[mi][3],
                             bh[2 * ni], bh[2 * ni + 1]);
                }
        }
        __syncthreads();
    }

    // ---- epilogue: direct fp32 stores ----
    const int r_base = m0 + wm * 64 + (lane >> 2);
    const int c_base = n0 + wn * 32 + (lane & 3) * 2;
    #pragma unroll
    for (int mi = 0; mi < 4; mi++) {
        #pragma unroll
        for (int ni = 0; ni < 4; ni++) {
            const int col = c_base + ni * 8;
            if (col < NT) {
                const int row0 = r_base + mi * 16;
                float2 v0 = make_float2(acc[mi][ni][0], acc[mi][ni][1]);
                float2 v1 = make_float2(acc[mi][ni][2], acc[mi][ni][3]);
                *reinterpret_cast<float2*>(out + ((size_t)(b * C_ + row0)) * NT + col) = v0;
                *reinterpret_cast<float2*>(out + ((size_t)(b * C_ + row0 + 8)) * NT + col) = v1;
            }
        }
    }
}

// ---------------------------------------------------------------------------
extern "C" void kernel_launch(void* const* d_in, const int* in_sizes, int n_in,
                              void* d_out, int out_size) {
    const float* x     = (const float*)d_in[0];
    const float* W     = (const float*)d_in[1];
    const float* alpha = (const float*)d_in[2];
    float* out = (float*)d_out;

    cudaFuncSetAttribute(k3_mma, cudaFuncAttributeMaxDynamicSharedMemorySize, K3_SMEM);

    k1_pool<<<dim3(C_, B_), 384>>>(x, W, alpha);
    k2_att <<<dim3(C_, B_), 256>>>();
    k3_mma <<<dim3((NT + 127) / 128, C_ / 128, B_), 256, K3_SMEM>>>(out);
}

// round 7
// speedup vs baseline: 2.3596x; 1.2575x over previous
#include <cuda_runtime.h>
#include <cuda_fp16.h>
#include <cstdint>

// Shapes (fixed)
#define B_   64
#define C_   256
#define N_   307
#define T_   12
#define NT   3684          // N_*T_
#define NT4  921           // NT/4

// ------------------------- scratch (__device__ globals) ---------------------
__device__ float g_k [B_ * C_ * T_];
__device__ float g_kW[B_ * C_ * T_];
__device__ __half g_xh[(size_t)B_ * C_ * NT];   // fp16 hi of x
__device__ __half g_xl[(size_t)B_ * C_ * NT];   // fp16 lo of x (residual)
__device__ __half g_a [(size_t)B_ * C_ * C_];   // fp16 attention

// ------------------------- PTX helpers (portable, sm_80+) -------------------
__device__ __forceinline__ uint32_t smem_u32(const void* p) {
    uint32_t a;
    asm("{ .reg .u64 t; cvta.to.shared.u64 t, %1; cvt.u32.u64 %0, t; }" : "=r"(a) : "l"(p));
    return a;
}
#define CP_ASYNC16(s, g) \
    asm volatile("cp.async.cg.shared.global [%0], [%1], 16;" :: "r"(s), "l"(g))
#define CP_ASYNC8Z(s, g, sz) \
    asm volatile("cp.async.ca.shared.global [%0], [%1], 8, %2;" :: "r"(s), "l"(g), "r"(sz))
#define CP_COMMIT() asm volatile("cp.async.commit_group;" ::: "memory")
#define CP_WAIT(n)  asm volatile("cp.async.wait_group %0;" :: "n"(n) : "memory")

#define LDSM_X4(r0, r1, r2, r3, a) \
    asm volatile("ldmatrix.sync.aligned.m8n8.x4.shared.b16 {%0,%1,%2,%3}, [%4];" \
        : "=r"(r0), "=r"(r1), "=r"(r2), "=r"(r3) : "r"(a))
#define LDSM_X4T(r0, r1, r2, r3, a) \
    asm volatile("ldmatrix.sync.aligned.m8n8.x4.trans.shared.b16 {%0,%1,%2,%3}, [%4];" \
        : "=r"(r0), "=r"(r1), "=r"(r2), "=r"(r3) : "r"(a))

#define MMA16816(d, a0, a1, a2, a3, b0, b1) \
    asm volatile("mma.sync.aligned.m16n8k16.row.col.f32.f16.f16.f32 " \
        "{%0,%1,%2,%3}, {%4,%5,%6,%7}, {%8,%9}, {%0,%1,%2,%3};" \
        : "+f"((d)[0]), "+f"((d)[1]), "+f"((d)[2]), "+f"((d)[3]) \
        : "r"(a0), "r"(a1), "r"(a2), "r"(a3), "r"(b0), "r"(b1))

// ---------------------------------------------------------------------------
// k1: pooled keys + kW, fused with fp16 hi/lo split-write of x.
// 384 threads; float4 per thread; a float4 never straddles a t=12 boundary
// (4*j4 mod 12 in {0,4,8}), so node index i = j4/3 is constant per float4.
// ---------------------------------------------------------------------------
__global__ __launch_bounds__(384) void k1_pool(const float* __restrict__ x,
                                               const float* __restrict__ W,
                                               const float* __restrict__ alpha) {
    __shared__ float sal[N_];
    __shared__ float sredf[384 * 4];
    __shared__ float kk[T_];

    const int tid = threadIdx.x;
    const int c = blockIdx.x, b = blockIdx.y;

    for (int i = tid; i < N_; i += 384) sal[i] = alpha[i];
    __syncthreads();

    const size_t rowoff = (size_t)(b * C_ + c) * NT;
    const float4* xp4 = reinterpret_cast<const float4*>(x + rowoff);
    __half* xh = g_xh + rowoff;
    __half* xl = g_xl + rowoff;

    float4 acc = make_float4(0.f, 0.f, 0.f, 0.f);
    #pragma unroll
    for (int u = 0; u < 3; u++) {
        const int j4 = tid + u * 384;
        if (j4 < NT4) {
            const float4 v = xp4[j4];
            const float a = sal[j4 / 3];
            acc.x += v.x * a; acc.y += v.y * a; acc.z += v.z * a; acc.w += v.w * a;

            union { __half h[4]; uint2 u2; } H, L;
            H.h[0] = __float2half(v.x); L.h[0] = __float2half(v.x - __half2float(H.h[0]));
            H.h[1] = __float2half(v.y); L.h[1] = __float2half(v.y - __half2float(H.h[1]));
            H.h[2] = __float2half(v.z); L.h[2] = __float2half(v.z - __half2float(H.h[2]));
            H.h[3] = __float2half(v.w); L.h[3] = __float2half(v.w - __half2float(H.h[3]));
            reinterpret_cast<uint2*>(xh)[j4] = H.u2;
            reinterpret_cast<uint2*>(xl)[j4] = L.u2;
        }
    }
    sredf[tid * 4 + 0] = acc.x;
    sredf[tid * 4 + 1] = acc.y;
    sredf[tid * 4 + 2] = acc.z;
    sredf[tid * 4 + 3] = acc.w;
    __syncthreads();

    if (tid < T_) {
        const int g = tid >> 2, e = tid & 3;   // t = 4*g + e; contributors have tid%3==g
        float s = 0.f;
        for (int q = 0; q < 128; q++) s += sredf[(3 * q + g) * 4 + e];
        kk[tid] = s;
        g_k[(b * C_ + c) * T_ + tid] = s;
    }
    __syncthreads();
    if (tid < T_) {
        float s = 0.f;
        #pragma unroll
        for (int t = 0; t < T_; t++) s += kk[t] * W[t * T_ + tid];
        g_kW[(b * C_ + c) * T_ + tid] = s;
    }
}

// ---------------------------------------------------------------------------
// k2: scores + softmax -> att, written as single fp16.
// ---------------------------------------------------------------------------
__global__ __launch_bounds__(256) void k2_att() {
    __shared__ float kb[C_ * 13];
    __shared__ float kw[T_];
    __shared__ float red[8];

    const int tid = threadIdx.x;
    const int c = blockIdx.x, b = blockIdx.y;

    for (int idx = tid; idx < C_ * T_; idx += 256)
        kb[(idx / T_) * 13 + (idx % T_)] = g_k[b * C_ * T_ + idx];
    if (tid < T_) kw[tid] = g_kW[(b * C_ + c) * T_ + tid];
    __syncthreads();

    float s = 0.f;
    #pragma unroll
    for (int t = 0; t < T_; t++) s += kw[t] * kb[tid * 13 + t];

    float m = s;
    #pragma unroll
    for (int o = 16; o; o >>= 1) m = fmaxf(m, __shfl_xor_sync(0xffffffffu, m, o));
    if ((tid & 31) == 0) red[tid >> 5] = m;
    __syncthreads();
    float bm = red[0];
    #pragma unroll
    for (int w = 1; w < 8; w++) bm = fmaxf(bm, red[w]);

    const float p = __expf(s - bm);

    float ps = p;
    #pragma unroll
    for (int o = 16; o; o >>= 1) ps += __shfl_xor_sync(0xffffffffu, ps, o);
    __syncthreads();
    if ((tid & 31) == 0) red[tid >> 5] = ps;
    __syncthreads();
    float tot = 0.f;
    #pragma unroll
    for (int w = 0; w < 8; w++) tot += red[w];

    g_a[((size_t)(b * C_ + c)) * C_ + tid] = __float2half(p / tot);
}

// ---------------------------------------------------------------------------
// k3: out[b] = att[b] @ x[b] via mma.sync fp16, 2 terms:
// a_fp16 * x_hi + a_fp16 * x_lo  (dropped A_lo @ X ~ 2^-12 normwise).
// Block 128x128, K-chunk 32, 16 warps (4m x 4n), warp tile 32x32.
// 3-stage cp.async ring, ONE __syncthreads per chunk.
// A [m][k] pad 40; B [k][n] gmem layout pad 136 + ldmatrix.trans.
// ---------------------------------------------------------------------------
#define BK 32
#define AS_STRIDE 40                       // halves; 80 B rows (conflict-free ldsm)
#define BS_STRIDE 136                      // halves; 272 B rows (conflict-free ldsm)
#define AS_BYTES (128 * AS_STRIDE * 2)     // 10240
#define BS_BYTES (BK * BS_STRIDE * 2)      // 8704
#define ST_A  0
#define ST_BH AS_BYTES
#define ST_BL (AS_BYTES + BS_BYTES)
#define STAGE_BYTES (AS_BYTES + 2 * BS_BYTES)       // 27648
#define K3_SMEM (3 * STAGE_BYTES)                   // 82944

__global__ __launch_bounds__(512, 1) void k3_mma(float* __restrict__ out) {
    extern __shared__ char smem[];
    const uint32_t sbase = smem_u32(smem);
    const int tid = threadIdx.x, wid = tid >> 5, lane = tid & 31;
    const int b = blockIdx.z;
    const int m0 = blockIdx.y * 128;
    const int n0 = blockIdx.x * 128;
    const int wm = wid >> 2;               // 0..3 -> 32-row band
    const int wn = wid & 3;                // 0..3 -> 32-col band

    const __half* A  = g_a  + ((size_t)(b * C_ + m0)) * C_;
    const __half* Xh = g_xh + (size_t)b * C_ * NT;
    const __half* Xl = g_xl + (size_t)b * C_ * NT;

    // ---- async stage loader (512 threads) ----
    auto load_stage = [&](int kc) {
        const int k0 = kc * BK;
        const uint32_t st = sbase + (kc % 3) * STAGE_BYTES;
        // A: 128 rows x 32 k halves = 8192 B; one 16B chunk per thread
        {
            const int r = tid >> 2, cc = tid & 3;
            const uint32_t so = (uint32_t)(r * (AS_STRIDE * 2) + cc * 16);
            CP_ASYNC16(st + ST_A + so, (const char*)(A + (size_t)r * C_ + k0 + cc * 8));
        }
        // B: 32 k-rows x 128 n halves, 8B chunks (1024 per array), 2 per thread
        #pragma unroll
        for (int it = 0; it < 2; it++) {
            const int q = tid + it * 512;
            const int kr = q >> 5, nc = q & 31;
            const int col = n0 + nc * 4;
            const uint32_t sz = (col < NT) ? 8u : 0u;
            const size_t go = (size_t)(k0 + kr) * NT + (col < NT ? col : 0);
            const uint32_t so = (uint32_t)(kr * (BS_STRIDE * 2) + nc * 8);
            CP_ASYNC8Z(st + ST_BH + so, (const char*)(Xh + go), sz);
            CP_ASYNC8Z(st + ST_BL + so, (const char*)(Xl + go), sz);
        }
        CP_COMMIT();
    };

    float acc[2][4][4];
    #pragma unroll
    for (int i = 0; i < 2; i++)
        #pragma unroll
        for (int j = 0; j < 4; j++)
            #pragma unroll
            for (int e = 0; e < 4; e++) acc[i][j][e] = 0.f;

    load_stage(0);
    load_stage(1);

    for (int kc = 0; kc < 8; kc++) {
        if (kc == 7) { CP_WAIT(0); } else { CP_WAIT(1); }   // stage kc resident
        __syncthreads();                                     // also protects (kc+2)%3 reuse
        if (kc + 2 < 8) load_stage(kc + 2);

        const uint32_t st = sbase + (kc % 3) * STAGE_BYTES;

        #pragma unroll
        for (int ks = 0; ks < 2; ks++) {
            const int kk0 = ks * 16;
            // A fragments: 2 m-tiles (shared by both terms)
            uint32_t af[2][4];
            {
                const int arow = wm * 32 + (lane & 15);
                const int akc = kk0 + (lane >> 4) * 8;
                #pragma unroll
                for (int mi = 0; mi < 2; mi++) {
                    const uint32_t ao = (uint32_t)((arow + mi * 16) * (AS_STRIDE * 2) + akc * 2);
                    LDSM_X4(af[mi][0], af[mi][1], af[mi][2], af[mi][3], st + ST_A + ao);
                }
            }
            // B fragments: 4 n8-tiles x (hi, lo)
            uint32_t bh[8], bl[8];
            {
                const int brow = kk0 + (lane & 15);
                const int bnc = wn * 32 + (lane >> 4) * 8;
                #pragma unroll
                for (int g = 0; g < 2; g++) {
                    const uint32_t bo = (uint32_t)(brow * (BS_STRIDE * 2) + (bnc + g * 16) * 2);
                    LDSM_X4T(bh[4 * g + 0], bh[4 * g + 1], bh[4 * g + 2], bh[4 * g + 3],
                             st + ST_BH + bo);
                    LDSM_X4T(bl[4 * g + 0], bl[4 * g + 1], bl[4 * g + 2], bl[4 * g + 3],
                             st + ST_BL + bo);
                }
            }
            #pragma unroll
            for (int mi = 0; mi < 2; mi++)
                #pragma unroll
                for (int ni = 0; ni < 4; ni++) {
                    MMA16816(acc[mi][ni], af[mi][0], af[mi][1], af[mi][2], af[mi][3],
                             bh[2 * ni], bh[2 * ni + 1]);
                    MMA16816(acc[mi][ni], af[mi][0], af[mi][1], af[mi][2], af[mi][3],
                             bl[2 * ni], bl[2 * ni + 1]);
                }
        }
    }

    // ---- epilogue: direct fp32 stores ----
    const int r_base = m0 + wm * 32 + (lane >> 2);
    const int c_base = n0 + wn * 32 + (lane & 3) * 2;
    #pragma unroll
    for (int mi = 0; mi < 2; mi++) {
        #pragma unroll
        for (int ni = 0; ni < 4; ni++) {
            const int col = c_base + ni * 8;
            if (col < NT) {
                const int row0 = r_base + mi * 16;
                float2 v0 = make_float2(acc[mi][ni][0], acc[mi][ni][1]);
                float2 v1 = make_float2(acc[mi][ni][2], acc[mi][ni][3]);
                *reinterpret_cast<float2*>(out + ((size_t)(b * C_ + row0)) * NT + col) = v0;
                *reinterpret_cast<float2*>(out + ((size_t)(b * C_ + row0 + 8)) * NT + col) = v1;
            }
        }
    }
}

// ---------------------------------------------------------------------------
extern "C" void kernel_launch(void* const* d_in, const int* in_sizes, int n_in,
                              void* d_out, int out_size) {
    const float* x     = (const float*)d_in[0];
    const float* W     = (const float*)d_in[1];
    const float* alpha = (const float*)d_in[2];
    float* out = (float*)d_out;

    cudaFuncSetAttribute(k3_mma, cudaFuncAttributeMaxDynamicSharedMemorySize, K3_SMEM);

    k1_pool<<<dim3(C_, B_), 384>>>(x, W, alpha);
    k2_att <<<dim3(C_, B_), 256>>>();
    k3_mma <<<dim3((NT + 127) / 128, C_ / 128, B_), 512, K3_SMEM>>>(out);
}